// round 3
// baseline (speedup 1.0000x reference)
#include <cuda_runtime.h>

#define B_TOTAL   131072
#define NBLOCKS   2048
#define NTHREADS  256
#define WPB       8
#define ROWS_PER_WARP (B_TOTAL / (NBLOCKS * WPB))   // 8
#define FULL      0xFFFFFFFFu

// deterministic two-stage reduction scratch (no allocation allowed)
__device__ double   g_partials[NBLOCKS * 2];
__device__ unsigned g_count = 0;

__device__ __forceinline__ float fsqrt_approx(float x) {
    float r; asm("sqrt.approx.f32 %0, %1;" : "=f"(r) : "f"(x)); return r;
}

__global__ __launch_bounds__(NTHREADS)
void constraint_loss_fused(const float* __restrict__ pred,
                           const float* __restrict__ tgt,
                           const float* __restrict__ inp,
                           float* __restrict__ out)
{
    __shared__ double s_red[WPB][2];
    __shared__ bool   s_is_last;

    const int warp  = threadIdx.x >> 5;
    const int lane  = threadIdx.x & 31;
    const int gwarp = blockIdx.x * WPB + warp;
    const int stride = NBLOCKS * WPB;

    const float4* p4 = (const float4*)pred;
    const float4* t4 = (const float4*)tgt;

    float  mse_acc = 0.0f;
    double ob_acc  = 0.0;        // obstacle term: linear -> defer reduction
    double dyn_acc = 0.0;        // per-row norms (lane 0 only)

    // ---- initial row load (registers, no smem) ----
    int row = gwarp;
    size_t base = (size_t)row * 60;
    float4 A  = p4[base + lane];
    float4 TA = t4[base + lane];
    float4 B  = make_float4(0.f, 0.f, 0.f, 0.f);
    float4 TB = make_float4(0.f, 0.f, 0.f, 0.f);
    if (lane < 28) { B = p4[base + 32 + lane]; TB = t4[base + 32 + lane]; }
    float iv = (lane < 13) ? inp[(size_t)row * 13 + lane] : 0.f;

    #pragma unroll 1
    for (int it = 0; it < ROWS_PER_WARP; ++it) {
        // ---- prefetch next row (clamped on last iter -> L1 hits) ----
        int nrow = row + stride;
        int prow = (it + 1 < ROWS_PER_WARP) ? nrow : row;
        size_t nb = (size_t)prow * 60;
        float4 nA  = p4[nb + lane];
        float4 nTA = t4[nb + lane];
        float4 nB  = make_float4(0.f, 0.f, 0.f, 0.f);
        float4 nTB = make_float4(0.f, 0.f, 0.f, 0.f);
        if (lane < 28) { nB = p4[nb + 32 + lane]; nTB = t4[nb + 32 + lane]; }
        float niv = (lane < 13) ? inp[(size_t)prow * 13 + lane] : 0.f;

        // ---- broadcast inputs row from lanes 0..12 ----
        float x0_0 = __shfl_sync(FULL, iv, 0);
        float x0_1 = __shfl_sync(FULL, iv, 1);
        float x0_2 = __shfl_sync(FULL, iv, 2);
        float x0_3 = __shfl_sync(FULL, iv, 3);
        float o0x  = __shfl_sync(FULL, iv, 4);
        float o0y  = __shfl_sync(FULL, iv, 5);
        float o0r  = __shfl_sync(FULL, iv, 6);
        float o1x  = __shfl_sync(FULL, iv, 7);
        float o1y  = __shfl_sync(FULL, iv, 8);
        float o1r  = __shfl_sync(FULL, iv, 9);
        float o2x  = __shfl_sync(FULL, iv, 10);
        float o2y  = __shfl_sync(FULL, iv, 11);
        float o2r  = __shfl_sync(FULL, iv, 12);
        float rad2_0 = (o0r + 2.0f) * (o0r + 2.0f);
        float rad2_1 = (o1r + 2.0f) * (o1r + 2.0f);
        float rad2_2 = (o2r + 2.0f) * (o2r + 2.0f);

        // ---- fused MSE ----
        {
            float d0 = A.x - TA.x, d1 = A.y - TA.y, d2 = A.z - TA.z, d3 = A.w - TA.w;
            mse_acc += d0 * d0 + d1 * d1 + d2 * d2 + d3 * d3;
            float e0 = B.x - TB.x, e1 = B.y - TB.y, e2 = B.z - TB.z, e3 = B.w - TB.w;
            if (lane < 28) mse_acc += e0 * e0 + e1 * e1 + e2 * e2 + e3 * e3;
        }

        float r0 = 0.f, r1 = 0.f, r2 = 0.f, r3 = 0.f;
        float ob_row = 0.f;

        // ============ round 1: timestep k = lane (x_k in own A) ============
        {
            float p0 = __shfl_up_sync(FULL, A.x, 1);
            float p1 = __shfl_up_sync(FULL, A.y, 1);
            float p2 = __shfl_up_sync(FULL, A.z, 1);
            float p3 = __shfl_up_sync(FULL, A.w, 1);
            if (lane == 0) { p0 = x0_0; p1 = x0_1; p2 = x0_2; p3 = x0_3; }

            int usrc = 8 + (lane >> 1);
            float s0 = __shfl_sync(FULL, B.x, usrc);
            float s1 = __shfl_sync(FULL, B.y, usrc);
            float s2 = __shfl_sync(FULL, B.z, usrc);
            float s3 = __shfl_sync(FULL, B.w, usrc);
            float ua = (lane & 1) ? s2 : s0;    // accel
            float uw = (lane & 1) ? s3 : s1;    // omega

            float c, s;
            __sincosf(p2, &s, &c);
            r0 = A.x - (p0 + p3 * c * 0.25f);
            r1 = A.y - (p1 + p3 * s * 0.25f);
            r2 = A.z - (p2 + uw * 0.25f);
            r3 = A.w - (p3 + ua * 0.25f);

            float dx, dy;
            dx = A.x - o0x; dy = A.y - o0y;
            ob_row += fsqrt_approx(dx * dx + dy * dy) - rad2_0;
            dx = A.x - o1x; dy = A.y - o1y;
            ob_row += fsqrt_approx(dx * dx + dy * dy) - rad2_1;
            dx = A.x - o2x; dy = A.y - o2y;
            ob_row += fsqrt_approx(dx * dx + dy * dy) - rad2_2;
        }

        // ============ round 2: timestep k = 32 + lane (lanes 0..7) ============
        {
            // prev x_{31+lane}: lane 0 <- A(31), lanes 1..7 <- B(lane-1)
            float tx = (lane == 31) ? A.x : B.x;
            float ty = (lane == 31) ? A.y : B.y;
            float tz = (lane == 31) ? A.z : B.z;
            float tw = (lane == 31) ? A.w : B.w;
            int psrc = (lane + 31) & 31;
            float q0 = __shfl_sync(FULL, tx, psrc);
            float q1 = __shfl_sync(FULL, ty, psrc);
            float q2 = __shfl_sync(FULL, tz, psrc);
            float q3 = __shfl_sync(FULL, tw, psrc);

            int usrc = 24 + (lane >> 1);
            float s0 = __shfl_sync(FULL, B.x, usrc);
            float s1 = __shfl_sync(FULL, B.y, usrc);
            float s2 = __shfl_sync(FULL, B.z, usrc);
            float s3 = __shfl_sync(FULL, B.w, usrc);

            if (lane < 8) {
                float ua = (lane & 1) ? s2 : s0;
                float uw = (lane & 1) ? s3 : s1;
                float c, s;
                __sincosf(q2, &s, &c);
                r0 += B.x - (q0 + q3 * c * 0.25f);
                r1 += B.y - (q1 + q3 * s * 0.25f);
                r2 += B.z - (q2 + uw * 0.25f);
                r3 += B.w - (q3 + ua * 0.25f);

                float dx, dy;
                dx = B.x - o0x; dy = B.y - o0y;
                ob_row += fsqrt_approx(dx * dx + dy * dy) - rad2_0;
                dx = B.x - o1x; dy = B.y - o1y;
                ob_row += fsqrt_approx(dx * dx + dy * dy) - rad2_1;
                dx = B.x - o2x; dy = B.y - o2y;
                ob_row += fsqrt_approx(dx * dx + dy * dy) - rad2_2;
            }
        }

        // ---- per-row warp reduce of dyn residual only ----
        #pragma unroll
        for (int off = 16; off; off >>= 1) {
            r0 += __shfl_xor_sync(FULL, r0, off);
            r1 += __shfl_xor_sync(FULL, r1, off);
            r2 += __shfl_xor_sync(FULL, r2, off);
            r3 += __shfl_xor_sync(FULL, r3, off);
        }
        if (lane == 0)
            dyn_acc += (double)fsqrt_approx(r0 * r0 + r1 * r1 + r2 * r2 + r3 * r3);

        ob_acc += (double)ob_row;     // deferred reduction (linear term)

        // ---- rotate prefetched row in ----
        row = nrow;
        A = nA; B = nB; TA = nTA; TB = nTB; iv = niv;
    }

    // ---- end-of-kernel reductions ----
    #pragma unroll
    for (int off = 16; off; off >>= 1) {
        mse_acc += __shfl_xor_sync(FULL, mse_acc, off);
        ob_acc  += __shfl_xor_sync(FULL, ob_acc,  off);
    }
    if (lane == 0) {
        s_red[warp][0] = (double)mse_acc;
        s_red[warp][1] = dyn_acc + ob_acc;
    }
    __syncthreads();
    if (threadIdx.x == 0) {
        double m = 0.0, c = 0.0;
        #pragma unroll
        for (int w = 0; w < WPB; w++) { m += s_red[w][0]; c += s_red[w][1]; }
        g_partials[blockIdx.x * 2 + 0] = m;
        g_partials[blockIdx.x * 2 + 1] = c;
        __threadfence();
        unsigned ticket = atomicAdd(&g_count, 1u);
        s_is_last = (ticket == (unsigned)(gridDim.x - 1));
    }
    __syncthreads();

    // ---- last block: deterministic fixed-order final sum ----
    if (s_is_last) {
        __threadfence();
        __shared__ double sm[NTHREADS];
        __shared__ double sc[NTHREADS];
        double m = 0.0, c = 0.0;
        for (int i = threadIdx.x; i < NBLOCKS; i += NTHREADS) {
            m += g_partials[2 * i + 0];
            c += g_partials[2 * i + 1];
        }
        sm[threadIdx.x] = m;
        sc[threadIdx.x] = c;
        __syncthreads();
        for (int s = NTHREADS / 2; s > 0; s >>= 1) {
            if (threadIdx.x < s) {
                sm[threadIdx.x] += sm[threadIdx.x + s];
                sc[threadIdx.x] += sc[threadIdx.x + s];
            }
            __syncthreads();
        }
        if (threadIdx.x == 0) {
            double mse = sm[0] / ((double)B_TOTAL * 240.0);
            double con = sc[0] / (double)B_TOTAL;
            out[0] = (float)(mse + con);
            g_count = 0;      // reset for next graph replay
        }
    }
}

extern "C" void kernel_launch(void* const* d_in, const int* in_sizes, int n_in,
                              void* d_out, int out_size)
{
    const float* pred = (const float*)d_in[0];
    const float* tgt  = (const float*)d_in[1];
    const float* inp  = (const float*)d_in[2];
    float* out = (float*)d_out;

    constraint_loss_fused<<<NBLOCKS, NTHREADS>>>(pred, tgt, inp, out);
}

// round 4
// speedup vs baseline: 1.0617x; 1.0617x over previous
#include <cuda_runtime.h>

#define B_TOTAL   131072
#define ROW_F     240
#define NBLOCKS   2048
#define NTHREADS  256
#define WPB       8
#define FULL      0xFFFFFFFFu

// deterministic two-stage reduction scratch (no allocation allowed)
__device__ double   g_partials[NBLOCKS * 2];
__device__ unsigned g_count = 0;

__device__ __forceinline__ float fsqrt_approx(float x) {
    float r; asm("sqrt.approx.f32 %0, %1;" : "=f"(r) : "f"(x)); return r;
}

__global__ __launch_bounds__(NTHREADS, 8)   // force <=32 regs -> full occupancy
void constraint_loss_fused(const float* __restrict__ pred,
                           const float* __restrict__ tgt,
                           const float* __restrict__ inp,
                           float* __restrict__ out)
{
    __shared__ float  s_pred[WPB][ROW_F];
    __shared__ double s_red[WPB][2];
    __shared__ bool   s_is_last;

    const int warp = threadIdx.x >> 5;
    const int lane = threadIdx.x & 31;
    const int gwarp = blockIdx.x * WPB + warp;
    const int totalWarps = NBLOCKS * WPB;

    float mse_acc = 0.0f;
    float ob_acc  = 0.0f;   // obstacle term: linear -> defer reduction to end
    float dyn_acc = 0.0f;   // per-row norms (lane 0 only)

    for (int row = gwarp; row < B_TOTAL; row += totalWarps) {
        const float4* p4 = (const float4*)(pred + (size_t)row * ROW_F);
        const float4* t4 = (const float4*)(tgt  + (size_t)row * ROW_F);
        float4* s4 = (float4*)s_pred[warp];

        // ---- phase 1: coalesced stream, fused MSE, stage pred in smem ----
        #pragma unroll
        for (int j = lane; j < 60; j += 32) {
            float4 p = p4[j];
            float4 t = t4[j];
            float d0 = p.x - t.x, d1 = p.y - t.y;
            float d2 = p.z - t.z, d3 = p.w - t.w;
            mse_acc += d0 * d0 + d1 * d1 + d2 * d2 + d3 * d3;
            s4[j] = p;
        }

        // ---- inputs row (uniform across warp -> broadcast loads) ----
        const float* irow = inp + (size_t)row * 13;
        float x0_0 = irow[0],  x0_1 = irow[1],  x0_2 = irow[2], x0_3 = irow[3];
        float o0x = irow[4],  o0y = irow[5],  o0r = irow[6];
        float o1x = irow[7],  o1y = irow[8],  o1r = irow[9];
        float o2x = irow[10], o2y = irow[11], o2r = irow[12];
        float rad2_0 = (o0r + 2.0f) * (o0r + 2.0f);
        float rad2_1 = (o1r + 2.0f) * (o1r + 2.0f);
        float rad2_2 = (o2r + 2.0f) * (o2r + 2.0f);

        __syncwarp();

        // ---- phase 2: timesteps distributed over lanes ----
        float r0 = 0.f, r1 = 0.f, r2 = 0.f, r3 = 0.f;
        #pragma unroll
        for (int k = lane; k < 40; k += 32) {
            const float* xk = &s_pred[warp][4 * k];
            float xk0 = xk[0], xk1 = xk[1], xk2 = xk[2], xk3 = xk[3];

            float p0, p1, p2, p3;
            if (k == 0) {
                p0 = x0_0; p1 = x0_1; p2 = x0_2; p3 = x0_3;
            } else {
                const float* pk = &s_pred[warp][4 * (k - 1)];
                p0 = pk[0]; p1 = pk[1]; p2 = pk[2]; p3 = pk[3];
            }
            float u0 = s_pred[warp][160 + 2 * k];
            float u1 = s_pred[warp][161 + 2 * k];

            float c, s;
            __sincosf(p2, &s, &c);
            r0 += xk0 - (p0 + p3 * c * 0.25f);
            r1 += xk1 - (p1 + p3 * s * 0.25f);
            r2 += xk2 - (p2 + u1 * 0.25f);
            r3 += xk3 - (p3 + u0 * 0.25f);

            float dx, dy;
            dx = xk0 - o0x; dy = xk1 - o0y;
            ob_acc += fsqrt_approx(dx * dx + dy * dy) - rad2_0;
            dx = xk0 - o1x; dy = xk1 - o1y;
            ob_acc += fsqrt_approx(dx * dx + dy * dy) - rad2_1;
            dx = xk0 - o2x; dy = xk1 - o2y;
            ob_acc += fsqrt_approx(dx * dx + dy * dy) - rad2_2;
        }

        // ---- per-row warp reduce of dyn residual 4-vector only ----
        #pragma unroll
        for (int off = 16; off; off >>= 1) {
            r0 += __shfl_xor_sync(FULL, r0, off);
            r1 += __shfl_xor_sync(FULL, r1, off);
            r2 += __shfl_xor_sync(FULL, r2, off);
            r3 += __shfl_xor_sync(FULL, r3, off);
        }
        if (lane == 0)
            dyn_acc += fsqrt_approx(r0 * r0 + r1 * r1 + r2 * r2 + r3 * r3);

        __syncwarp();   // protect s_pred before next row overwrites it
    }

    // ---- end-of-kernel warp reductions ----
    #pragma unroll
    for (int off = 16; off; off >>= 1) {
        mse_acc += __shfl_xor_sync(FULL, mse_acc, off);
        ob_acc  += __shfl_xor_sync(FULL, ob_acc,  off);
    }
    if (lane == 0) {
        s_red[warp][0] = (double)mse_acc;
        s_red[warp][1] = (double)dyn_acc + (double)ob_acc;
    }
    __syncthreads();
    if (threadIdx.x == 0) {
        double m = 0.0, c = 0.0;
        #pragma unroll
        for (int w = 0; w < WPB; w++) { m += s_red[w][0]; c += s_red[w][1]; }
        g_partials[blockIdx.x * 2 + 0] = m;
        g_partials[blockIdx.x * 2 + 1] = c;
        __threadfence();
        unsigned ticket = atomicAdd(&g_count, 1u);
        s_is_last = (ticket == (unsigned)(NBLOCKS - 1));
    }
    __syncthreads();

    // ---- last block: deterministic fixed-order final sum ----
    if (s_is_last) {
        __threadfence();
        __shared__ double sm[NTHREADS];
        __shared__ double sc[NTHREADS];
        double m = 0.0, c = 0.0;
        for (int i = threadIdx.x; i < NBLOCKS; i += NTHREADS) {
            m += g_partials[2 * i + 0];
            c += g_partials[2 * i + 1];
        }
        sm[threadIdx.x] = m;
        sc[threadIdx.x] = c;
        __syncthreads();
        for (int s = NTHREADS / 2; s > 0; s >>= 1) {
            if (threadIdx.x < s) {
                sm[threadIdx.x] += sm[threadIdx.x + s];
                sc[threadIdx.x] += sc[threadIdx.x + s];
            }
            __syncthreads();
        }
        if (threadIdx.x == 0) {
            double mse = sm[0] / ((double)B_TOTAL * (double)ROW_F);
            double con = sc[0] / (double)B_TOTAL;
            out[0] = (float)(mse + con);
            g_count = 0;      // reset for next graph replay
        }
    }
}

extern "C" void kernel_launch(void* const* d_in, const int* in_sizes, int n_in,
                              void* d_out, int out_size)
{
    const float* pred = (const float*)d_in[0];
    const float* tgt  = (const float*)d_in[1];
    const float* inp  = (const float*)d_in[2];
    float* out = (float*)d_out;

    constraint_loss_fused<<<NBLOCKS, NTHREADS>>>(pred, tgt, inp, out);
}

// round 7
// speedup vs baseline: 1.0705x; 1.0083x over previous
#include <cuda_runtime.h>

#define B_TOTAL   131072
#define ROW_F     240
#define NBLOCKS   2048
#define NTHREADS  256
#define WPB       8
#define RPW       8          // rows per warp = B_TOTAL / (NBLOCKS*WPB)
#define STRIDE    (NBLOCKS * WPB)
#define FULL      0xFFFFFFFFu

// deterministic two-stage reduction scratch (no allocation allowed)
__device__ double   g_partials[NBLOCKS * 2];
__device__ unsigned g_count = 0;

__device__ __forceinline__ float fsqrt_approx(float x) {
    float r; asm("sqrt.approx.f32 %0, %1;" : "=f"(r) : "f"(x)); return r;
}
__device__ __forceinline__ void cp_async16(unsigned int saddr, const void* gptr) {
    asm volatile("cp.async.ca.shared.global [%0], [%1], 16;" :: "r"(saddr), "l"(gptr));
}

__global__ __launch_bounds__(NTHREADS)
void constraint_loss_fused(const float* __restrict__ pred,
                           const float* __restrict__ tgt,
                           const float* __restrict__ inp,
                           float* __restrict__ out)
{
    __shared__ float  s_pred[WPB][2][ROW_F];   // double-buffered pred rows
    __shared__ float  s_inp[WPB][RPW][13];     // all input rows, hoisted
    __shared__ double s_red[WPB][2];
    __shared__ bool   s_is_last;

    const int warp  = threadIdx.x >> 5;
    const int lane  = threadIdx.x & 31;
    const int gwarp = blockIdx.x * WPB + warp;

    const float4* p4 = (const float4*)pred;
    const float4* t4 = (const float4*)tgt;

    // ---- hoist all 8 input rows for this warp into smem (once) ----
    for (int idx = lane; idx < RPW * 13; idx += 32) {
        int ri = idx / 13, f = idx - ri * 13;
        s_inp[warp][ri][f] = inp[(size_t)(gwarp + ri * STRIDE) * 13 + f];
    }

    // ---- preload pred row 0 into buffer 0 via cp.async ----
    {
        size_t base = (size_t)gwarp * 60;
        unsigned int sb = (unsigned int)__cvta_generic_to_shared(&s_pred[warp][0][0]);
        cp_async16(sb + 16u * lane, p4 + base + lane);
        if (lane < 28) cp_async16(sb + 16u * (32 + lane), p4 + base + 32 + lane);
    }
    asm volatile("cp.async.commit_group;");

    float mse_acc = 0.0f;
    float ob_acc  = 0.0f;
    float dyn_acc = 0.0f;

    #pragma unroll 1
    for (int it = 0; it < RPW; ++it) {
        const int   buf  = it & 1;
        const int   row  = gwarp + it * STRIDE;
        const size_t base = (size_t)row * 60;

        // ---- issue prefetch of NEXT pred row into other buffer ----
        if (it + 1 < RPW) {
            size_t nb = base + (size_t)STRIDE * 60;
            unsigned int sb = (unsigned int)__cvta_generic_to_shared(&s_pred[warp][buf ^ 1][0]);
            cp_async16(sb + 16u * lane, p4 + nb + lane);
            if (lane < 28) cp_async16(sb + 16u * (32 + lane), p4 + nb + 32 + lane);
            asm volatile("cp.async.commit_group;");
        }

        // ---- tgt loads for current row (overlap with cp.async wait) ----
        float4 tA = t4[base + lane];
        float4 tB = make_float4(0.f, 0.f, 0.f, 0.f);
        if (lane < 28) tB = t4[base + 32 + lane];

        // ---- wait current pred buffer ----
        if (it + 1 < RPW) asm volatile("cp.async.wait_group 1;");
        else              asm volatile("cp.async.wait_group 0;");
        __syncwarp();

        const float*  bufp = s_pred[warp][buf];
        const float4* b4   = (const float4*)bufp;

        // pA = float4 #lane  (== x_lane);  pB = float4 #(32+lane)
        float4 pA = b4[lane];
        float4 pB = make_float4(0.f, 0.f, 0.f, 0.f);
        if (lane < 28) pB = b4[32 + lane];

        // ---- fused MSE ----
        {
            float d0 = pA.x - tA.x, d1 = pA.y - tA.y, d2 = pA.z - tA.z, d3 = pA.w - tA.w;
            mse_acc += d0 * d0 + d1 * d1 + d2 * d2 + d3 * d3;
            if (lane < 28) {
                float e0 = pB.x - tB.x, e1 = pB.y - tB.y, e2 = pB.z - tB.z, e3 = pB.w - tB.w;
                mse_acc += e0 * e0 + e1 * e1 + e2 * e2 + e3 * e3;
            }
        }

        // ---- inputs from smem (broadcast LDS, off critical path) ----
        const float* irow = s_inp[warp][it];
        float o0x = irow[4],  o0y = irow[5];
        float o1x = irow[7],  o1y = irow[8];
        float o2x = irow[10], o2y = irow[11];
        float rad2_0 = (irow[6]  + 2.0f) * (irow[6]  + 2.0f);
        float rad2_1 = (irow[9]  + 2.0f) * (irow[9]  + 2.0f);
        float rad2_2 = (irow[12] + 2.0f) * (irow[12] + 2.0f);

        float r0, r1, r2, r3;
        float ob_row = 0.f;

        // ===== round 1: timestep k = lane (x_k == pA) =====
        {
            float p0, p1, p2, p3;
            if (lane == 0) { p0 = irow[0]; p1 = irow[1]; p2 = irow[2]; p3 = irow[3]; }
            else {
                const float* pk = &bufp[4 * (lane - 1)];
                p0 = pk[0]; p1 = pk[1]; p2 = pk[2]; p3 = pk[3];
            }
            float2 u = *(const float2*)&bufp[160 + 2 * lane];

            float c, s;
            __sincosf(p2, &s, &c);
            r0 = pA.x - (p0 + p3 * c * 0.25f);
            r1 = pA.y - (p1 + p3 * s * 0.25f);
            r2 = pA.z - (p2 + u.y * 0.25f);
            r3 = pA.w - (p3 + u.x * 0.25f);

            float dx, dy;
            dx = pA.x - o0x; dy = pA.y - o0y;
            ob_row += fsqrt_approx(dx * dx + dy * dy) - rad2_0;
            dx = pA.x - o1x; dy = pA.y - o1y;
            ob_row += fsqrt_approx(dx * dx + dy * dy) - rad2_1;
            dx = pA.x - o2x; dy = pA.y - o2y;
            ob_row += fsqrt_approx(dx * dx + dy * dy) - rad2_2;
        }

        // ===== round 2: timestep k = 32 + lane (lanes 0..7; x_k == pB) =====
        if (lane < 8) {
            int k = 32 + lane;
            const float* pk = &bufp[4 * (k - 1)];
            float p0 = pk[0], p1 = pk[1], p2 = pk[2], p3 = pk[3];
            float2 u = *(const float2*)&bufp[160 + 2 * k];

            float c, s;
            __sincosf(p2, &s, &c);
            r0 += pB.x - (p0 + p3 * c * 0.25f);
            r1 += pB.y - (p1 + p3 * s * 0.25f);
            r2 += pB.z - (p2 + u.y * 0.25f);
            r3 += pB.w - (p3 + u.x * 0.25f);

            float dx, dy;
            dx = pB.x - o0x; dy = pB.y - o0y;
            ob_row += fsqrt_approx(dx * dx + dy * dy) - rad2_0;
            dx = pB.x - o1x; dy = pB.y - o1y;
            ob_row += fsqrt_approx(dx * dx + dy * dy) - rad2_1;
            dx = pB.x - o2x; dy = pB.y - o2y;
            ob_row += fsqrt_approx(dx * dx + dy * dy) - rad2_2;
        }

        // ---- warp butterfly reduce of dyn residual 4-vector ----
        #pragma unroll
        for (int off = 16; off; off >>= 1) {
            r0 += __shfl_xor_sync(FULL, r0, off);
            r1 += __shfl_xor_sync(FULL, r1, off);
            r2 += __shfl_xor_sync(FULL, r2, off);
            r3 += __shfl_xor_sync(FULL, r3, off);
        }
        if (lane == 0)
            dyn_acc += fsqrt_approx(r0 * r0 + r1 * r1 + r2 * r2 + r3 * r3);

        ob_acc += ob_row;          // linear term: defer cross-lane reduce to end

        __syncwarp();              // all reads of buf done before it's refilled
    }

    // ---- end-of-kernel reductions ----
    #pragma unroll
    for (int off = 16; off; off >>= 1) {
        mse_acc += __shfl_xor_sync(FULL, mse_acc, off);
        ob_acc  += __shfl_xor_sync(FULL, ob_acc,  off);
    }
    if (lane == 0) {
        s_red[warp][0] = (double)mse_acc;
        s_red[warp][1] = (double)dyn_acc + (double)ob_acc;
    }
    __syncthreads();
    if (threadIdx.x == 0) {
        double m = 0.0, c = 0.0;
        #pragma unroll
        for (int w = 0; w < WPB; w++) { m += s_red[w][0]; c += s_red[w][1]; }
        g_partials[blockIdx.x * 2 + 0] = m;
        g_partials[blockIdx.x * 2 + 1] = c;
        __threadfence();
        unsigned ticket = atomicAdd(&g_count, 1u);
        s_is_last = (ticket == (unsigned)(NBLOCKS - 1));
    }
    __syncthreads();

    // ---- last block: deterministic fixed-order final sum ----
    if (s_is_last) {
        __threadfence();
        __shared__ double sm[NTHREADS];
        __shared__ double sc[NTHREADS];
        double m = 0.0, c = 0.0;
        for (int i = threadIdx.x; i < NBLOCKS; i += NTHREADS) {
            m += g_partials[2 * i + 0];
            c += g_partials[2 * i + 1];
        }
        sm[threadIdx.x] = m;
        sc[threadIdx.x] = c;
        __syncthreads();
        for (int s = NTHREADS / 2; s > 0; s >>= 1) {
            if (threadIdx.x < s) {
                sm[threadIdx.x] += sm[threadIdx.x + s];
                sc[threadIdx.x] += sc[threadIdx.x + s];
            }
            __syncthreads();
        }
        if (threadIdx.x == 0) {
            double mse = sm[0] / ((double)B_TOTAL * (double)ROW_F);
            double con = sc[0] / (double)B_TOTAL;
            out[0] = (float)(mse + con);
            g_count = 0;      // reset for next graph replay
        }
    }
}

extern "C" void kernel_launch(void* const* d_in, const int* in_sizes, int n_in,
                              void* d_out, int out_size)
{
    const float* pred = (const float*)d_in[0];
    const float* tgt  = (const float*)d_in[1];
    const float* inp  = (const float*)d_in[2];
    float* out = (float*)d_out;

    constraint_loss_fused<<<NBLOCKS, NTHREADS>>>(pred, tgt, inp, out);
}